// round 2
// baseline (speedup 1.0000x reference)
#include <cuda_runtime.h>
#include <math.h>

#define B_ 64
#define S_ 512
#define DIN 1024
#define HID 4096
#define HS 1024
#define NCTA 128

// ---------------------------------------------------------------------------
// f32x2 packed-FMA helpers (sm_100+)
// ---------------------------------------------------------------------------
#define FMA2(acc, a, b) \
    asm("fma.rn.f32x2 %0, %1, %2, %0;" : "+l"(acc) : "l"(a), "l"(b))
#define PACK2(d, x) \
    asm("mov.b64 %0, {%1, %1};" : "=l"(d) : "f"(x))
#define UNPACK2(lo, hi, v) \
    asm("mov.b64 {%0, %1}, %2;" : "=f"(lo), "=f"(hi) : "l"(v))

// Scratch (static device globals; no runtime allocation).
__device__ float g_xg[(size_t)S_ * B_ * HID];   // [s][b][4096] input-gate preact
__device__ float g_h2[2][B_ * HS];              // double-buffered hidden state
__device__ unsigned g_bar;                      // grid barrier counter

// ---------------------------------------------------------------------------
// Init: reset barrier + zero h buffer 0 (graph replays re-run this).
// ---------------------------------------------------------------------------
__global__ void init_state() {
    int t = blockIdx.x * blockDim.x + threadIdx.x;
    if (t == 0) g_bar = 0u;
    if (t < B_ * HS) g_h2[0][t] = 0.0f;
}

// ---------------------------------------------------------------------------
// xg[m][n] = sum_k x_row(m)[k] * wx[n][k] + bx[n] + bh[n]
//   m = s*64 + b ; x_row(m) = x + (b*512 + s)*1024
// 128x128x16 tiles, 256 threads, 8x8 micro-tile via f32x2 packed FMA.
// ---------------------------------------------------------------------------
__global__ __launch_bounds__(256, 2) void xg_gemm(const float* __restrict__ x,
                                                  const float* __restrict__ wx,
                                                  const float* __restrict__ bx,
                                                  const float* __restrict__ bh) {
    __shared__ float As[16][132];   // [k][m]
    __shared__ float Bs[16][132];   // [k][n]

    const int tid = threadIdx.x;
    const int m0 = blockIdx.y * 128;
    const int n0 = blockIdx.x * 128;
    const int tx = tid & 15;        // n-group
    const int ty = tid >> 4;        // m-group

    unsigned long long acc[8][4];
#pragma unroll
    for (int i = 0; i < 8; i++)
#pragma unroll
        for (int j = 0; j < 4; j++) acc[i][j] = 0ull;

    for (int k0 = 0; k0 < DIN; k0 += 16) {
#pragma unroll
        for (int l = 0; l < 2; l++) {
            int v = tid * 2 + l;
            int row = v >> 2;
            int kv = v & 3;
            int m = m0 + row;
            int b = m & 63;
            int s = m >> 6;
            float4 f = *(const float4*)(x + ((size_t)b * S_ + s) * DIN + k0 + kv * 4);
            As[kv * 4 + 0][row] = f.x;
            As[kv * 4 + 1][row] = f.y;
            As[kv * 4 + 2][row] = f.z;
            As[kv * 4 + 3][row] = f.w;
        }
#pragma unroll
        for (int l = 0; l < 2; l++) {
            int v = tid * 2 + l;
            int row = v >> 2;
            int kv = v & 3;
            float4 f = *(const float4*)(wx + (size_t)(n0 + row) * DIN + k0 + kv * 4);
            Bs[kv * 4 + 0][row] = f.x;
            Bs[kv * 4 + 1][row] = f.y;
            Bs[kv * 4 + 2][row] = f.z;
            Bs[kv * 4 + 3][row] = f.w;
        }
        __syncthreads();

#pragma unroll
        for (int kk = 0; kk < 16; kk++) {
            float4 a0 = *(const float4*)&As[kk][ty * 8];
            float4 a1 = *(const float4*)&As[kk][ty * 8 + 4];
            ulonglong2 bA = *(const ulonglong2*)&Bs[kk][tx * 8];
            ulonglong2 bB = *(const ulonglong2*)&Bs[kk][tx * 8 + 4];
            float av[8] = {a0.x, a0.y, a0.z, a0.w, a1.x, a1.y, a1.z, a1.w};
#pragma unroll
            for (int i = 0; i < 8; i++) {
                unsigned long long a2;
                PACK2(a2, av[i]);
                FMA2(acc[i][0], a2, bA.x);
                FMA2(acc[i][1], a2, bA.y);
                FMA2(acc[i][2], a2, bB.x);
                FMA2(acc[i][3], a2, bB.y);
            }
        }
        __syncthreads();
    }

    float bias[8];
#pragma unroll
    for (int j = 0; j < 8; j++) {
        int n = n0 + tx * 8 + j;
        bias[j] = bx[n] + bh[n];
    }
#pragma unroll
    for (int i = 0; i < 8; i++) {
        int m = m0 + ty * 8 + i;
        float* dst = g_xg + (size_t)m * HID + n0 + tx * 8;
#pragma unroll
        for (int j = 0; j < 4; j++) {
            float lo, hi;
            UNPACK2(lo, hi, acc[i][j]);
            dst[2 * j + 0] = lo + bias[2 * j + 0];
            dst[2 * j + 1] = hi + bias[2 * j + 1];
        }
    }
}

// ---------------------------------------------------------------------------
// Persistent recurrent kernel. 128 CTAs x 256 threads (co-resident on 148 SMs).
// CTA j-chunk: 8 hidden units -> 32 gate columns {g*1024 + j0 + 0..7}.
// wh rows cached in smem once. One global barrier per step.
// ---------------------------------------------------------------------------
__device__ __forceinline__ float sigf(float x) {
    return 1.0f / (1.0f + __expf(-x));
}
__device__ __forceinline__ float tanhfast(float x) {
    float ax = fabsf(x);
    float e = __expf(-2.0f * ax);
    float r = (1.0f - e) / (1.0f + e);
    return copysignf(r, x);
}

__device__ __forceinline__ void grid_barrier(unsigned target) {
    __syncthreads();
    if (threadIdx.x == 0) {
        __threadfence();
        atomicAdd(&g_bar, 1u);
        while (*((volatile unsigned*)&g_bar) < target) {
        }
        __threadfence();
    }
    __syncthreads();
}

// smem layout (floats):
//   whs   [1024][32]         32768
//   hs    [8 warps][128][12] 12288   (per-warp staged h chunk, transposed)
//   gates [64][33]           2112
//   csm   [64][8]            512
#define SM_WHS 0
#define SM_HS 32768
#define SM_GATES (SM_HS + 8 * 128 * 12)
#define SM_CSM (SM_GATES + 64 * 33)
#define SM_FLOATS (SM_CSM + 64 * 8)

__global__ void __launch_bounds__(256, 1)
lstm_persist(const float* __restrict__ wh, float* __restrict__ out, int do_tail) {
    extern __shared__ float sm[];
    float* whs = sm + SM_WHS;
    float* gates = sm + SM_GATES;
    float* csm = sm + SM_CSM;

    const int tid = threadIdx.x;
    const int j0 = blockIdx.x * 8;
    const int col = tid & 31;          // gate column 0..31
    const int wrp = tid >> 5;          // warp 0..7
    const int b0 = wrp * 8;            // this warp's batch base
    float* hw = sm + SM_HS + wrp * (128 * 12);

    // --- one-time: load this CTA's 32 wh rows transposed into smem ---
    {
        int c = tid & 31;
        int n = (c >> 3) * HS + j0 + (c & 7);       // gate*1024 + j0 + jl
        const float* wrow = wh + (size_t)n * HS;
        int kbase = (tid >> 5) * 128;
#pragma unroll
        for (int l = 0; l < 32; l++) {
            int k = kbase + l * 4;
            float4 v = *(const float4*)(wrow + k);
            whs[(k + 0) * 32 + c] = v.x;
            whs[(k + 1) * 32 + c] = v.y;
            whs[(k + 2) * 32 + c] = v.z;
            whs[(k + 3) * 32 + c] = v.w;
        }
    }
    for (int i = tid; i < 64 * 8; i += 256) csm[i] = 0.0f;
    __syncthreads();

    const int lane = tid & 31;
    const int bl = lane >> 2;          // 0..7 : batch within warp group
    const int kq = lane & 3;           // 0..3 : k sub-stripe

    for (int s = 0; s < S_; s++) {
        const int p = s & 1;
        const float* hsrc = g_h2[p];

        unsigned long long acc0 = 0ull, acc1 = 0ull, acc2 = 0ull, acc3 = 0ull;

        // prologue: stage chunk 0
        float4 r[8];
        {
            const float* src = hsrc + (size_t)(b0 + bl) * HS;
#pragma unroll
            for (int i = 0; i < 8; i++)
                r[i] = *(const float4*)(src + kq * 4 + i * 16);
#pragma unroll
            for (int i = 0; i < 8; i++) {
                int k = kq * 4 + i * 16;
                hw[(k + 0) * 12 + bl] = r[i].x;
                hw[(k + 1) * 12 + bl] = r[i].y;
                hw[(k + 2) * 12 + bl] = r[i].z;
                hw[(k + 3) * 12 + bl] = r[i].w;
            }
            __syncwarp();
        }

        for (int ch = 0; ch < 8; ch++) {
            const int koff = ch * 128;
            if (ch < 7) {
                const float* src = hsrc + (size_t)(b0 + bl) * HS + (koff + 128);
#pragma unroll
                for (int i = 0; i < 8; i++)
                    r[i] = *(const float4*)(src + kq * 4 + i * 16);
            }
            // compute 128 k-steps from hw
#pragma unroll 16
            for (int kk = 0; kk < 128; kk++) {
                const float* hrow = hw + kk * 12;
                ulonglong2 aA = *(const ulonglong2*)(hrow);
                ulonglong2 aB = *(const ulonglong2*)(hrow + 4);
                float bv = whs[(koff + kk) * 32 + col];
                unsigned long long b2;
                PACK2(b2, bv);
                FMA2(acc0, aA.x, b2);
                FMA2(acc1, aA.y, b2);
                FMA2(acc2, aB.x, b2);
                FMA2(acc3, aB.y, b2);
            }
            __syncwarp();
            if (ch < 7) {
#pragma unroll
                for (int i = 0; i < 8; i++) {
                    int k = kq * 4 + i * 16;
                    hw[(k + 0) * 12 + bl] = r[i].x;
                    hw[(k + 1) * 12 + bl] = r[i].y;
                    hw[(k + 2) * 12 + bl] = r[i].z;
                    hw[(k + 3) * 12 + bl] = r[i].w;
                }
                __syncwarp();
            }
        }

        // scatter accumulators to gates smem for cross-thread gate combine
        {
            float lo, hi;
            UNPACK2(lo, hi, acc0);
            gates[(b0 + 0) * 33 + col] = lo;
            gates[(b0 + 1) * 33 + col] = hi;
            UNPACK2(lo, hi, acc1);
            gates[(b0 + 2) * 33 + col] = lo;
            gates[(b0 + 3) * 33 + col] = hi;
            UNPACK2(lo, hi, acc2);
            gates[(b0 + 4) * 33 + col] = lo;
            gates[(b0 + 5) * 33 + col] = hi;
            UNPACK2(lo, hi, acc3);
            gates[(b0 + 6) * 33 + col] = lo;
            gates[(b0 + 7) * 33 + col] = hi;
        }
        __syncthreads();

        // activations + state update: 128 threads, 4 hidden units each
        if (tid < 128) {
            const int b = tid >> 1;
            const int jq = (tid & 1) * 4;
            const float* xp = g_xg + ((size_t)s * B_ + b) * HID + j0 + jq;
            float4 xi = *(const float4*)(xp + 0 * HS);
            float4 xf = *(const float4*)(xp + 1 * HS);
            float4 xg4 = *(const float4*)(xp + 2 * HS);
            float4 xo = *(const float4*)(xp + 3 * HS);
            float4 cold = *(const float4*)&csm[b * 8 + jq];
            const float* grow = gates + b * 33;

            float xiv[4] = {xi.x, xi.y, xi.z, xi.w};
            float xfv[4] = {xf.x, xf.y, xf.z, xf.w};
            float xgv[4] = {xg4.x, xg4.y, xg4.z, xg4.w};
            float xov[4] = {xo.x, xo.y, xo.z, xo.w};
            float cv[4] = {cold.x, cold.y, cold.z, cold.w};
            float hv[4];
#pragma unroll
            for (int q = 0; q < 4; q++) {
                int jl = jq + q;
                float gi = xiv[q] + grow[0 + jl];
                float gf = xfv[q] + grow[8 + jl];
                float gg = xgv[q] + grow[16 + jl];
                float go = xov[q] + grow[24 + jl];
                float iv = sigf(gi);
                float fv = sigf(gf);
                float gv = tanhfast(gg);
                float ov = sigf(go);
                float c = fv * cv[q] + iv * gv;
                cv[q] = c;
                hv[q] = ov * tanhfast(c);
            }
            float4 cnew = make_float4(cv[0], cv[1], cv[2], cv[3]);
            float4 hnew = make_float4(hv[0], hv[1], hv[2], hv[3]);
            *(float4*)&csm[b * 8 + jq] = cnew;
            *(float4*)(g_h2[p ^ 1] + (size_t)b * HS + j0 + jq) = hnew;
            *(float4*)(out + ((size_t)b * S_ + s) * HS + j0 + jq) = hnew;
        }

        grid_barrier((unsigned)(s + 1) * (unsigned)gridDim.x);
    }

    // tail: final (h, c)
    if (do_tail && tid < 128) {
        const int b = tid >> 1;
        const int jq = (tid & 1) * 4;
        const size_t base = (size_t)B_ * S_ * HS;
        float4 hfin = *(const float4*)(g_h2[0] + (size_t)b * HS + j0 + jq);
        float4 cfin = *(const float4*)&csm[b * 8 + jq];
        *(float4*)(out + base + (size_t)b * HS + j0 + jq) = hfin;
        *(float4*)(out + base + (size_t)B_ * HS + (size_t)b * HS + j0 + jq) = cfin;
    }
}

extern "C" void kernel_launch(void* const* d_in, const int* in_sizes, int n_in,
                              void* d_out, int out_size) {
    const float* x = (const float*)d_in[0];
    const float* wx = (const float*)d_in[1];
    const float* wh = (const float*)d_in[2];
    const float* bx = (const float*)d_in[3];
    const float* bh = (const float*)d_in[4];
    float* out = (float*)d_out;

    init_state<<<(B_ * HS + 255) / 256, 256>>>();

    dim3 ga(HID / 128, (S_ * B_) / 128);   // (32, 256)
    xg_gemm<<<ga, 256>>>(x, wx, bx, bh);

    const size_t smem = (size_t)SM_FLOATS * sizeof(float);
    cudaFuncSetAttribute(lstm_persist, cudaFuncAttributeMaxDynamicSharedMemorySize,
                         (int)smem);
    int do_tail =
        ((long long)out_size >= (long long)B_ * S_ * HS + 2LL * B_ * HS) ? 1 : 0;
    lstm_persist<<<NCTA, 256, smem>>>(wh, out, do_tail);
}

// round 4
// speedup vs baseline: 1.5042x; 1.5042x over previous
#include <cuda_runtime.h>
#include <cuda_bf16.h>
#include <math.h>
#include <stdint.h>

#define B_ 64
#define S_ 512
#define DIN 1024
#define HID 4096
#define HS 1024
#define NCTA 128
#define THREADS 256

// ---------------------------------------------------------------------------
// helpers
// ---------------------------------------------------------------------------
#define FMA2(acc, a, b) \
    asm("fma.rn.f32x2 %0, %1, %2, %0;" : "+l"(acc) : "l"(a), "l"(b))
#define PACK2(d, x) \
    asm("mov.b64 %0, {%1, %1};" : "=l"(d) : "f"(x))
#define UNPACK2(lo, hi, v) \
    asm("mov.b64 {%0, %1}, %2;" : "=f"(lo), "=f"(hi) : "l"(v))

__device__ __forceinline__ uint32_t smem_to_u32(const void* p) {
    uint32_t a;
    asm("{ .reg .u64 t; cvta.to.shared.u64 t, %1; cvt.u32.u64 %0, t; }"
        : "=r"(a) : "l"(p));
    return a;
}

#define LDSM4(r0, r1, r2, r3, addr)                                        \
    asm volatile("ldmatrix.sync.aligned.m8n8.x4.shared.b16 {%0,%1,%2,%3}, [%4];" \
                 : "=r"(r0), "=r"(r1), "=r"(r2), "=r"(r3) : "r"(addr))

#define MMA16816(c, a0, a1, a2, a3, b0, b1)                                \
    asm volatile("mma.sync.aligned.m16n8k16.row.col.f32.bf16.bf16.f32 "    \
                 "{%0,%1,%2,%3}, {%4,%5,%6,%7}, {%8,%9}, {%0,%1,%2,%3};"   \
                 : "+f"((c)[0]), "+f"((c)[1]), "+f"((c)[2]), "+f"((c)[3])  \
                 : "r"(a0), "r"(a1), "r"(a2), "r"(a3), "r"(b0), "r"(b1))

#define CP16(d, s) \
    asm volatile("cp.async.cg.shared.global [%0], [%1], 16;" :: "r"(d), "l"(s))
#define CPCOMMIT() asm volatile("cp.async.commit_group;" ::: "memory")

// ---------------------------------------------------------------------------
// Globals (static scratch)
// ---------------------------------------------------------------------------
__device__ float g_xg[(size_t)S_ * B_ * HID];    // [s][b][4096]
__device__ __nv_bfloat16 g_hbf[2][2][B_ * HS];   // [buf][hi/lo][b][k]
__device__ unsigned g_bar;

__global__ void init_state() {
    int t = blockIdx.x * blockDim.x + threadIdx.x;
    if (t == 0) g_bar = 0u;
    if (t < B_ * HS) {
        g_hbf[0][0][t] = __float2bfloat16(0.0f);
        g_hbf[0][1][t] = __float2bfloat16(0.0f);
    }
}

// ---------------------------------------------------------------------------
// xg GEMM (fp32 f32x2; known-good from round 2)
// ---------------------------------------------------------------------------
__global__ __launch_bounds__(256, 2) void xg_gemm(const float* __restrict__ x,
                                                  const float* __restrict__ wx,
                                                  const float* __restrict__ bx,
                                                  const float* __restrict__ bh) {
    __shared__ float As[16][132];
    __shared__ float Bs[16][132];

    const int tid = threadIdx.x;
    const int m0 = blockIdx.y * 128;
    const int n0 = blockIdx.x * 128;
    const int tx = tid & 15;
    const int ty = tid >> 4;

    unsigned long long acc[8][4];
#pragma unroll
    for (int i = 0; i < 8; i++)
#pragma unroll
        for (int j = 0; j < 4; j++) acc[i][j] = 0ull;

    for (int k0 = 0; k0 < DIN; k0 += 16) {
#pragma unroll
        for (int l = 0; l < 2; l++) {
            int v = tid * 2 + l;
            int row = v >> 2;
            int kv = v & 3;
            int m = m0 + row;
            int b = m & 63;
            int s = m >> 6;
            float4 f = *(const float4*)(x + ((size_t)b * S_ + s) * DIN + k0 + kv * 4);
            As[kv * 4 + 0][row] = f.x;
            As[kv * 4 + 1][row] = f.y;
            As[kv * 4 + 2][row] = f.z;
            As[kv * 4 + 3][row] = f.w;
        }
#pragma unroll
        for (int l = 0; l < 2; l++) {
            int v = tid * 2 + l;
            int row = v >> 2;
            int kv = v & 3;
            float4 f = *(const float4*)(wx + (size_t)(n0 + row) * DIN + k0 + kv * 4);
            Bs[kv * 4 + 0][row] = f.x;
            Bs[kv * 4 + 1][row] = f.y;
            Bs[kv * 4 + 2][row] = f.z;
            Bs[kv * 4 + 3][row] = f.w;
        }
        __syncthreads();

#pragma unroll
        for (int kk = 0; kk < 16; kk++) {
            float4 a0 = *(const float4*)&As[kk][ty * 8];
            float4 a1 = *(const float4*)&As[kk][ty * 8 + 4];
            ulonglong2 bA = *(const ulonglong2*)&Bs[kk][tx * 8];
            ulonglong2 bB = *(const ulonglong2*)&Bs[kk][tx * 8 + 4];
            float av[8] = {a0.x, a0.y, a0.z, a0.w, a1.x, a1.y, a1.z, a1.w};
#pragma unroll
            for (int i = 0; i < 8; i++) {
                unsigned long long a2;
                PACK2(a2, av[i]);
                FMA2(acc[i][0], a2, bA.x);
                FMA2(acc[i][1], a2, bA.y);
                FMA2(acc[i][2], a2, bB.x);
                FMA2(acc[i][3], a2, bB.y);
            }
        }
        __syncthreads();
    }

    float bias[8];
#pragma unroll
    for (int j = 0; j < 8; j++) {
        int n = n0 + tx * 8 + j;
        bias[j] = bx[n] + bh[n];
    }
#pragma unroll
    for (int i = 0; i < 8; i++) {
        int m = m0 + ty * 8 + i;
        float* dst = g_xg + (size_t)m * HID + n0 + tx * 8;
#pragma unroll
        for (int j = 0; j < 4; j++) {
            float lo, hi;
            UNPACK2(lo, hi, acc[i][j]);
            dst[2 * j + 0] = lo + bias[2 * j + 0];
            dst[2 * j + 1] = hi + bias[2 * j + 1];
        }
    }
}

// ---------------------------------------------------------------------------
// Persistent recurrence on mma.sync bf16 (3-term hi/lo split, fp32 acc)
// ---------------------------------------------------------------------------
__device__ __forceinline__ float sigf(float x) { return 1.0f / (1.0f + __expf(-x)); }
__device__ __forceinline__ float tanhfast(float x) {
    float ax = fabsf(x);
    float e = __expf(-2.0f * ax);
    float r = (1.0f - e) / (1.0f + e);
    return copysignf(r, x);
}

__device__ __forceinline__ void grid_barrier(unsigned target) {
    __syncthreads();
    if (threadIdx.x == 0) {
        __threadfence();
        atomicAdd(&g_bar, 1u);
        while (*((volatile unsigned*)&g_bar) < target) {
        }
        __threadfence();
    }
    __syncthreads();
}

// smem byte layout
//  wh_hi : 32 cols x 1024 k bf16, [col][k], XOR swizzle      65536
//  wh_lo : same                                               65536
//  hstage: 2 bufs x (hi 16K + lo 16K)                         65536
//  gates : 64 x 33 f32                                         8448
#define SM_WH_HI 0
#define SM_WH_LO 65536
#define SM_HST 131072
#define SM_GATES 196608
#define SMEM_TOTAL (SM_GATES + 64 * 33 * 4)

__global__ void __launch_bounds__(THREADS, 1)
lstm_persist(const float* __restrict__ wh, float* __restrict__ out, int do_tail) {
    extern __shared__ char smem[];
    uint32_t sb = smem_to_u32(smem);
    float* gates = (float*)(smem + SM_GATES);

    const int tid = threadIdx.x;
    const int wid = tid >> 5;
    const int lane = tid & 31;
    const int j0 = blockIdx.x * 8;

    // --- one-time: split this CTA's 32 wh rows into bf16 hi/lo smem ---
    {
        const int c = tid >> 3;                      // col 0..31
        const int kb = (tid & 7) * 128;              // k base
        const int n = (c >> 3) * HS + j0 + (c & 7);  // gate*1024 + j0 + unit
        const float* wr = wh + (size_t)n * HS;
        const uint32_t swz = (uint32_t)((c & 7) << 4);
#pragma unroll 4
        for (int i = 0; i < 32; i++) {
            int k = kb + i * 4;
            float4 w4 = *(const float4*)(wr + k);
            __nv_bfloat16 h0 = __float2bfloat16(w4.x);
            __nv_bfloat16 h1 = __float2bfloat16(w4.y);
            __nv_bfloat16 h2 = __float2bfloat16(w4.z);
            __nv_bfloat16 h3 = __float2bfloat16(w4.w);
            __nv_bfloat16 l0 = __float2bfloat16(w4.x - __bfloat162float(h0));
            __nv_bfloat16 l1 = __float2bfloat16(w4.y - __bfloat162float(h1));
            __nv_bfloat16 l2 = __float2bfloat16(w4.z - __bfloat162float(h2));
            __nv_bfloat16 l3 = __float2bfloat16(w4.w - __bfloat162float(h3));
            uint32_t off = (uint32_t)(c * 2048) + (((uint32_t)(k * 2)) ^ swz);
            *(__nv_bfloat162*)(smem + SM_WH_HI + off) = __nv_bfloat162(h0, h1);
            *(__nv_bfloat162*)(smem + SM_WH_HI + off + 4) = __nv_bfloat162(h2, h3);
            *(__nv_bfloat162*)(smem + SM_WH_LO + off) = __nv_bfloat162(l0, l1);
            *(__nv_bfloat162*)(smem + SM_WH_LO + off + 4) = __nv_bfloat162(l2, l3);
        }
    }
    __syncthreads();

    // warp tile: rows [wm, wm+16), cols [wn, wn+16)
    const int wm = (wid >> 1) << 4;
    const int wn = (wid & 1) << 4;

    // A ldmatrix lane addressing (16x16 tile, row-major, swizzled 256B rows)
    const int ar = wm + (lane & 15);
    const uint32_t a_row = (uint32_t)ar * 256;
    const uint32_t a_k2 = (uint32_t)((lane >> 4) << 4);   // +8k half -> +16B
    const uint32_t a_swz = (uint32_t)((ar & 7) << 4);

    // B ldmatrix lane addressing (cols as rows, 2048B col stride, swizzled)
    const int bc = wn + (lane & 7) + ((lane >> 4) << 3);
    const uint32_t b_row = (uint32_t)bc * 2048;
    const uint32_t b_k2 = (uint32_t)(((lane >> 3) & 1) << 4);
    const uint32_t b_swz = (uint32_t)((bc & 7) << 4);

    // cp.async staging assignment
    const int srow = tid >> 2;
    const int skq = (tid & 3) * 32;
    const uint32_t s_swz = (uint32_t)((srow & 7) << 4);

    float creg[8];
#pragma unroll
    for (int q = 0; q < 8; q++) creg[q] = 0.0f;

    for (int s = 0; s < S_; s++) {
        const int p = s & 1;
        const __nv_bfloat16* hh_g = g_hbf[p][0];
        const __nv_bfloat16* hl_g = g_hbf[p][1];

        // xg prefetch for this step (warps 0-1; hidden behind GEMM)
        float4 xgr[8];
        if (wid < 2) {
            int b = wid * 32 + lane;
            const float* xp = g_xg + ((size_t)s * B_ + b) * HID + j0;
#pragma unroll
            for (int g = 0; g < 4; g++) {
                xgr[g * 2 + 0] = *(const float4*)(xp + g * HS);
                xgr[g * 2 + 1] = *(const float4*)(xp + g * HS + 4);
            }
        }

        float cA[4] = {0.f, 0.f, 0.f, 0.f};
        float cB[4] = {0.f, 0.f, 0.f, 0.f};

        // stage chunk 0 -> buf 0
        {
            const __nv_bfloat16* sh = hh_g + srow * HS;
            const __nv_bfloat16* sl = hl_g + srow * HS;
            uint32_t dbase = sb + SM_HST + (uint32_t)srow * 256;
#pragma unroll
            for (int j = 0; j < 4; j++) {
                int ko = skq + j * 8;
                uint32_t sw = ((uint32_t)(ko * 2)) ^ s_swz;
                CP16(dbase + sw, sh + ko);
                CP16(dbase + 16384 + sw, sl + ko);
            }
            CPCOMMIT();
        }

#pragma unroll 1
        for (int ch = 0; ch < 8; ch++) {
            const uint32_t buf = (uint32_t)(ch & 1);
            if (ch < 7) {
                const int nk = (ch + 1) * 128;
                const __nv_bfloat16* sh = hh_g + srow * HS + nk;
                const __nv_bfloat16* sl = hl_g + srow * HS + nk;
                uint32_t dbase = sb + SM_HST + ((buf ^ 1u) * 32768u) +
                                 (uint32_t)srow * 256;
#pragma unroll
                for (int j = 0; j < 4; j++) {
                    int ko = skq + j * 8;
                    uint32_t sw = ((uint32_t)(ko * 2)) ^ s_swz;
                    CP16(dbase + sw, sh + ko);
                    CP16(dbase + 16384 + sw, sl + ko);
                }
                CPCOMMIT();
                asm volatile("cp.async.wait_group 1;" ::: "memory");
            } else {
                asm volatile("cp.async.wait_group 0;" ::: "memory");
            }
            __syncthreads();

            const uint32_t abase = sb + SM_HST + buf * 32768u;
            const uint32_t kch2 = (uint32_t)(ch * 256);   // chunk k-offset in bytes
#pragma unroll
            for (int k16 = 0; k16 < 8; k16++) {
                const uint32_t ka = (uint32_t)(k16 * 32);
                uint32_t aoff = a_row + ((ka + a_k2) ^ a_swz);
                uint32_t ah0, ah1, ah2, ah3, al0, al1, al2, al3;
                LDSM4(ah0, ah1, ah2, ah3, abase + aoff);
                LDSM4(al0, al1, al2, al3, abase + 16384u + aoff);
                uint32_t boff = b_row + ((kch2 + ka + b_k2) ^ b_swz);
                uint32_t bh0, bh1, bh2, bh3, bl0, bl1, bl2, bl3;
                LDSM4(bh0, bh1, bh2, bh3, sb + SM_WH_HI + boff);
                LDSM4(bl0, bl1, bl2, bl3, sb + SM_WH_LO + boff);

                MMA16816(cA, ah0, ah1, ah2, ah3, bh0, bh1);
                MMA16816(cB, ah0, ah1, ah2, ah3, bh2, bh3);
                MMA16816(cA, ah0, ah1, ah2, ah3, bl0, bl1);
                MMA16816(cB, ah0, ah1, ah2, ah3, bl2, bl3);
                MMA16816(cA, al0, al1, al2, al3, bh0, bh1);
                MMA16816(cB, al0, al1, al2, al3, bh2, bh3);
            }
            __syncthreads();
        }

        // scatter C frags to gates smem
        {
            const int tr = lane >> 2;
            const int tc = (lane & 3) * 2;
            const int br = wm + tr;
            gates[(br + 0) * 33 + wn + tc + 0] = cA[0];
            gates[(br + 0) * 33 + wn + tc + 1] = cA[1];
            gates[(br + 8) * 33 + wn + tc + 0] = cA[2];
            gates[(br + 8) * 33 + wn + tc + 1] = cA[3];
            gates[(br + 0) * 33 + wn + 8 + tc + 0] = cB[0];
            gates[(br + 0) * 33 + wn + 8 + tc + 1] = cB[1];
            gates[(br + 8) * 33 + wn + 8 + tc + 0] = cB[2];
            gates[(br + 8) * 33 + wn + 8 + tc + 1] = cB[3];
        }
        __syncthreads();

        // activations + state update (warps 0-1: one thread per batch)
        if (wid < 2) {
            const int b = wid * 32 + lane;
            const float* grow = gates + b * 33;
            float xi[8] = {xgr[0].x, xgr[0].y, xgr[0].z, xgr[0].w,
                           xgr[1].x, xgr[1].y, xgr[1].z, xgr[1].w};
            float xf[8] = {xgr[2].x, xgr[2].y, xgr[2].z, xgr[2].w,
                           xgr[3].x, xgr[3].y, xgr[3].z, xgr[3].w};
            float xg4[8] = {xgr[4].x, xgr[4].y, xgr[4].z, xgr[4].w,
                            xgr[5].x, xgr[5].y, xgr[5].z, xgr[5].w};
            float xo[8] = {xgr[6].x, xgr[6].y, xgr[6].z, xgr[6].w,
                           xgr[7].x, xgr[7].y, xgr[7].z, xgr[7].w};
            float hnew[8];
#pragma unroll
            for (int jl = 0; jl < 8; jl++) {
                float gi = grow[0 + jl] + xi[jl];
                float gf = grow[8 + jl] + xf[jl];
                float gg = grow[16 + jl] + xg4[jl];
                float go = grow[24 + jl] + xo[jl];
                float iv = sigf(gi);
                float fv = sigf(gf);
                float gv = tanhfast(gg);
                float ov = sigf(go);
                float c = fv * creg[jl] + iv * gv;
                creg[jl] = c;
                hnew[jl] = ov * tanhfast(c);
            }
            float* op = out + ((size_t)b * S_ + s) * HS + j0;
            *(float4*)(op + 0) = make_float4(hnew[0], hnew[1], hnew[2], hnew[3]);
            *(float4*)(op + 4) = make_float4(hnew[4], hnew[5], hnew[6], hnew[7]);

            union { __nv_bfloat162 v2[4]; uint4 u; } uh, ul;
#pragma unroll
            for (int q = 0; q < 4; q++) {
                float a = hnew[2 * q], bb = hnew[2 * q + 1];
                __nv_bfloat16 ha = __float2bfloat16(a);
                __nv_bfloat16 hb = __float2bfloat16(bb);
                __nv_bfloat16 la = __float2bfloat16(a - __bfloat162float(ha));
                __nv_bfloat16 lb = __float2bfloat16(bb - __bfloat162float(hb));
                uh.v2[q] = __nv_bfloat162(ha, hb);
                ul.v2[q] = __nv_bfloat162(la, lb);
            }
            *(uint4*)(&g_hbf[p ^ 1][0][b * HS + j0]) = uh.u;
            *(uint4*)(&g_hbf[p ^ 1][1][b * HS + j0]) = ul.u;

            if (do_tail && s == S_ - 1) {
                const size_t base = (size_t)B_ * S_ * HS;
                float* hp = out + base + (size_t)b * HS + j0;
                float* cp = out + base + (size_t)B_ * HS + (size_t)b * HS + j0;
                *(float4*)(hp + 0) = make_float4(hnew[0], hnew[1], hnew[2], hnew[3]);
                *(float4*)(hp + 4) = make_float4(hnew[4], hnew[5], hnew[6], hnew[7]);
                *(float4*)(cp + 0) = make_float4(creg[0], creg[1], creg[2], creg[3]);
                *(float4*)(cp + 4) = make_float4(creg[4], creg[5], creg[6], creg[7]);
            }
            __threadfence();
        }

        grid_barrier((unsigned)(s + 1) * (unsigned)gridDim.x);
    }
}

extern "C" void kernel_launch(void* const* d_in, const int* in_sizes, int n_in,
                              void* d_out, int out_size) {
    const float* x = (const float*)d_in[0];
    const float* wx = (const float*)d_in[1];
    const float* wh = (const float*)d_in[2];
    const float* bx = (const float*)d_in[3];
    const float* bh = (const float*)d_in[4];
    float* out = (float*)d_out;

    init_state<<<(B_ * HS + 255) / 256, 256>>>();

    dim3 ga(HID / 128, (S_ * B_) / 128);   // (32, 256)
    xg_gemm<<<ga, 256>>>(x, wx, bx, bh);

    cudaFuncSetAttribute(lstm_persist, cudaFuncAttributeMaxDynamicSharedMemorySize,
                         SMEM_TOTAL);
    int do_tail =
        ((long long)out_size >= (long long)B_ * S_ * HS + 2LL * B_ * HS) ? 1 : 0;
    lstm_persist<<<NCTA, THREADS, SMEM_TOTAL>>>(wh, out, do_tail);
}

// round 5
// speedup vs baseline: 2.8287x; 1.8806x over previous
#include <cuda_runtime.h>
#include <cuda_fp16.h>
#include <math.h>
#include <stdint.h>

#define B_ 64
#define S_ 512
#define DIN 1024
#define HID 4096
#define HS 1024
#define NCTA 128
#define THREADS 256

// ---------------------------------------------------------------------------
// helpers
// ---------------------------------------------------------------------------
__device__ __forceinline__ uint32_t smem_to_u32(const void* p) {
    uint32_t a;
    asm("{ .reg .u64 t; cvta.to.shared.u64 t, %1; cvt.u32.u64 %0, t; }"
        : "=r"(a) : "l"(p));
    return a;
}

#define LDSM4(r0, r1, r2, r3, addr)                                        \
    asm volatile("ldmatrix.sync.aligned.m8n8.x4.shared.b16 {%0,%1,%2,%3}, [%4];" \
                 : "=r"(r0), "=r"(r1), "=r"(r2), "=r"(r3) : "r"(addr))

#define MMA16816(c, a0, a1, a2, a3, b0, b1)                                \
    asm volatile("mma.sync.aligned.m16n8k16.row.col.f32.f16.f16.f32 "      \
                 "{%0,%1,%2,%3}, {%4,%5,%6,%7}, {%8,%9}, {%0,%1,%2,%3};"   \
                 : "+f"((c)[0]), "+f"((c)[1]), "+f"((c)[2]), "+f"((c)[3])  \
                 : "r"(a0), "r"(a1), "r"(a2), "r"(a3), "r"(b0), "r"(b1))

#define CP16(d, s) \
    asm volatile("cp.async.cg.shared.global [%0], [%1], 16;" :: "r"(d), "l"(s))
#define CPCOMMIT() asm volatile("cp.async.commit_group;" ::: "memory")
#define CPWAIT(n) asm volatile("cp.async.wait_group %0;" :: "n"(n) : "memory")

// ---------------------------------------------------------------------------
// Globals (static scratch)
// ---------------------------------------------------------------------------
__device__ float g_xg[(size_t)S_ * B_ * HID];     // [s][b][4096]
__device__ __half g_xh[(size_t)B_ * S_ * DIN];    // x as fp16, same layout
__device__ __half g_wxh[(size_t)HID * DIN];       // wx hi
__device__ __half g_wxl[(size_t)HID * DIN];       // wx lo (residual)
__device__ __half g_hh[2][B_ * HS];               // double-buffered hidden (fp16)
__device__ unsigned g_bar;

__global__ void init_state() {
    int t = blockIdx.x * blockDim.x + threadIdx.x;
    if (t == 0) g_bar = 0u;
    if (t < B_ * HS / 2) ((uint32_t*)g_hh[0])[t] = 0u;
}

// ---------------------------------------------------------------------------
// Convert x -> fp16, wx -> fp16 hi/lo
// ---------------------------------------------------------------------------
__global__ void convert_inputs(const float* __restrict__ x,
                               const float* __restrict__ wx) {
    int t = blockIdx.x * blockDim.x + threadIdx.x;
    int stride = gridDim.x * blockDim.x;
    // wx: HID*DIN = 4M floats
    for (int i = t; i < HID * DIN / 4; i += stride) {
        float4 w = ((const float4*)wx)[i];
        __half h0 = __float2half_rn(w.x);
        __half h1 = __float2half_rn(w.y);
        __half h2 = __float2half_rn(w.z);
        __half h3 = __float2half_rn(w.w);
        __half l0 = __float2half_rn(w.x - __half2float(h0));
        __half l1 = __float2half_rn(w.y - __half2float(h1));
        __half l2 = __float2half_rn(w.z - __half2float(h2));
        __half l3 = __float2half_rn(w.w - __half2float(h3));
        ((__half2*)g_wxh)[i * 2 + 0] = __half2(h0, h1);
        ((__half2*)g_wxh)[i * 2 + 1] = __half2(h2, h3);
        ((__half2*)g_wxl)[i * 2 + 0] = __half2(l0, l1);
        ((__half2*)g_wxl)[i * 2 + 1] = __half2(l2, l3);
    }
    // x: 32M floats
    for (int i = t; i < B_ * S_ * DIN / 4; i += stride) {
        float4 v = ((const float4*)x)[i];
        ((__half2*)g_xh)[i * 2 + 0] = __half2(__float2half_rn(v.x), __float2half_rn(v.y));
        ((__half2*)g_xh)[i * 2 + 1] = __half2(__float2half_rn(v.z), __float2half_rn(v.w));
    }
}

// ---------------------------------------------------------------------------
// xg GEMM via mma.sync (fp16 2-term): xg[m][n] = x[m]·wx[n] + bx[n] + bh[n]
// Tile 128x128, K-chunk 64, 2-stage cp.async, 8 warps (m64 x n32).
// smem: A 2x16KB, B 2x(hi 16KB + lo 16KB) = 96KB
// ---------------------------------------------------------------------------
#define XG_SA 0
#define XG_SB 32768
#define XG_SMEM 98304

__global__ void __launch_bounds__(256, 1)
xg_gemm_mma(const float* __restrict__ bx, const float* __restrict__ bh) {
    extern __shared__ char smem[];
    uint32_t sb = smem_to_u32(smem);
    const int tid = threadIdx.x;
    const int wid = tid >> 5;
    const int lane = tid & 31;
    const int m0 = blockIdx.x * 128;
    const int n0 = blockIdx.y * 128;
    const int wm = (wid >> 2) * 64;
    const int wn = (wid & 3) * 32;

    // staging assignment: 128 rows x 8 16B-chunks; A 4/thread, B 8/thread
    const int sr = tid >> 1;
    const int sq0 = (tid & 1) * 4;
    const uint32_t s_sw = (uint32_t)((sr & 7) << 4);
    const int am = m0 + sr;
    const __half* asrc = g_xh + ((size_t)((am & 63) * S_ + (am >> 6))) * DIN;
    const __half* bhsrc = g_wxh + (size_t)(n0 + sr) * DIN;
    const __half* blsrc = g_wxl + (size_t)(n0 + sr) * DIN;

    // ldmatrix addressing
    const uint32_t a_k2 = (uint32_t)((lane >> 4) << 4);
    uint32_t a_base[4], a_swz[4];
#pragma unroll
    for (int mi = 0; mi < 4; mi++) {
        int ar = wm + mi * 16 + (lane & 15);
        a_base[mi] = (uint32_t)ar * 128;
        a_swz[mi] = (uint32_t)((ar & 7) << 4);
    }
    const uint32_t b_k2 = (uint32_t)(((lane >> 3) & 1) << 4);
    uint32_t b_base[2], b_swz[2];
#pragma unroll
    for (int ni = 0; ni < 2; ni++) {
        int bc = wn + ni * 16 + (lane & 7) + ((lane >> 4) << 3);
        b_base[ni] = (uint32_t)bc * 128;
        b_swz[ni] = (uint32_t)((bc & 7) << 4);
    }

    float acc[4][4][4];
#pragma unroll
    for (int i = 0; i < 4; i++)
#pragma unroll
        for (int j = 0; j < 4; j++)
#pragma unroll
            for (int q = 0; q < 4; q++) acc[i][j][q] = 0.0f;

    // prologue: stage chunk 0 -> buf 0
    {
        uint32_t da = sb + XG_SA + (uint32_t)sr * 128;
        uint32_t db = sb + XG_SB + (uint32_t)sr * 128;
#pragma unroll
        for (int j = 0; j < 4; j++) {
            int q = sq0 + j;
            uint32_t sw = ((uint32_t)(q * 16)) ^ s_sw;
            CP16(da + sw, asrc + q * 8);
            CP16(db + sw, bhsrc + q * 8);
            CP16(db + 16384 + sw, blsrc + q * 8);
        }
        CPCOMMIT();
    }

#pragma unroll 1
    for (int ch = 0; ch < 16; ch++) {
        const uint32_t buf = (uint32_t)(ch & 1);
        if (ch < 15) {
            const int kb = (ch + 1) * 64;
            uint32_t da = sb + XG_SA + (buf ^ 1u) * 16384u + (uint32_t)sr * 128;
            uint32_t db = sb + XG_SB + (buf ^ 1u) * 32768u + (uint32_t)sr * 128;
#pragma unroll
            for (int j = 0; j < 4; j++) {
                int q = sq0 + j;
                uint32_t sw = ((uint32_t)(q * 16)) ^ s_sw;
                CP16(da + sw, asrc + kb + q * 8);
                CP16(db + sw, bhsrc + kb + q * 8);
                CP16(db + 16384 + sw, blsrc + kb + q * 8);
            }
            CPCOMMIT();
            CPWAIT(1);
        } else {
            CPWAIT(0);
        }
        __syncthreads();

        const uint32_t abase = sb + XG_SA + buf * 16384u;
        const uint32_t bbase = sb + XG_SB + buf * 32768u;
#pragma unroll
        for (int k16 = 0; k16 < 4; k16++) {
            const uint32_t ka = (uint32_t)(k16 * 32);
            uint32_t a[4][4];
#pragma unroll
            for (int mi = 0; mi < 4; mi++)
                LDSM4(a[mi][0], a[mi][1], a[mi][2], a[mi][3],
                      abase + a_base[mi] + ((ka + a_k2) ^ a_swz[mi]));
            uint32_t bhf[2][4], blf[2][4];
#pragma unroll
            for (int ni = 0; ni < 2; ni++) {
                uint32_t bo = b_base[ni] + ((ka + b_k2) ^ b_swz[ni]);
                LDSM4(bhf[ni][0], bhf[ni][1], bhf[ni][2], bhf[ni][3], bbase + bo);
                LDSM4(blf[ni][0], blf[ni][1], blf[ni][2], blf[ni][3],
                      bbase + 16384u + bo);
            }
#pragma unroll
            for (int mi = 0; mi < 4; mi++)
#pragma unroll
                for (int ni = 0; ni < 2; ni++) {
                    MMA16816(acc[mi][ni * 2 + 0], a[mi][0], a[mi][1], a[mi][2],
                             a[mi][3], bhf[ni][0], bhf[ni][1]);
                    MMA16816(acc[mi][ni * 2 + 1], a[mi][0], a[mi][1], a[mi][2],
                             a[mi][3], bhf[ni][2], bhf[ni][3]);
                    MMA16816(acc[mi][ni * 2 + 0], a[mi][0], a[mi][1], a[mi][2],
                             a[mi][3], blf[ni][0], blf[ni][1]);
                    MMA16816(acc[mi][ni * 2 + 1], a[mi][0], a[mi][1], a[mi][2],
                             a[mi][3], blf[ni][2], blf[ni][3]);
                }
        }
        __syncthreads();
    }

    // epilogue
    const int tr = lane >> 2;
    const int tc = (lane & 3) * 2;
#pragma unroll
    for (int ni = 0; ni < 4; ni++) {
        int n = n0 + wn + ni * 8 + tc;
        float b0 = bx[n] + bh[n];
        float b1 = bx[n + 1] + bh[n + 1];
#pragma unroll
        for (int mi = 0; mi < 4; mi++) {
            int mrow = m0 + wm + mi * 16 + tr;
            float* d0 = g_xg + (size_t)mrow * HID + n;
            float* d1 = g_xg + (size_t)(mrow + 8) * HID + n;
            *(float2*)d0 = make_float2(acc[mi][ni][0] + b0, acc[mi][ni][1] + b1);
            *(float2*)d1 = make_float2(acc[mi][ni][2] + b0, acc[mi][ni][3] + b1);
        }
    }
}

// ---------------------------------------------------------------------------
// Persistent recurrence: fp16 2-term, 4-deep cp.async pipeline
// ---------------------------------------------------------------------------
__device__ __forceinline__ float sigf(float x) { return 1.0f / (1.0f + __expf(-x)); }
__device__ __forceinline__ float tanhfast(float x) {
    float ax = fabsf(x);
    float e = __expf(-2.0f * ax);
    float r = (1.0f - e) / (1.0f + e);
    return copysignf(r, x);
}

__device__ __forceinline__ void grid_barrier(unsigned target) {
    __syncthreads();
    if (threadIdx.x == 0) {
        __threadfence();
        atomicAdd(&g_bar, 1u);
        while (*((volatile unsigned*)&g_bar) < target) {
        }
        __threadfence();
    }
    __syncthreads();
}

// smem layout (bytes)
#define SM_WH_HI 0
#define SM_WH_LO 65536
#define SM_HST 131072        /* 4 bufs x 16KB (64 rows x 128k fp16) */
#define SM_GATES 196608      /* 64 x 33 f32 */
#define SMEM_TOTAL (SM_GATES + 64 * 33 * 4)

__global__ void __launch_bounds__(THREADS, 1)
lstm_persist(const float* __restrict__ wh, float* __restrict__ out, int do_tail) {
    extern __shared__ char smem[];
    uint32_t sb = smem_to_u32(smem);
    float* gates = (float*)(smem + SM_GATES);

    const int tid = threadIdx.x;
    const int wid = tid >> 5;
    const int lane = tid & 31;
    const int j0 = blockIdx.x * 8;

    // --- one-time: split this CTA's 32 wh rows into fp16 hi/lo smem ---
    {
        const int c = tid >> 3;                      // col 0..31
        const int kb = (tid & 7) * 128;              // k base
        const int n = (c >> 3) * HS + j0 + (c & 7);  // gate*1024 + j0 + unit
        const float* wr = wh + (size_t)n * HS;
        const uint32_t swz = (uint32_t)((c & 7) << 4);
#pragma unroll 4
        for (int i = 0; i < 32; i++) {
            int k = kb + i * 4;
            float4 w4 = *(const float4*)(wr + k);
            __half h0 = __float2half_rn(w4.x);
            __half h1 = __float2half_rn(w4.y);
            __half h2 = __float2half_rn(w4.z);
            __half h3 = __float2half_rn(w4.w);
            __half l0 = __float2half_rn(w4.x - __half2float(h0));
            __half l1 = __float2half_rn(w4.y - __half2float(h1));
            __half l2 = __float2half_rn(w4.z - __half2float(h2));
            __half l3 = __float2half_rn(w4.w - __half2float(h3));
            uint32_t off = (uint32_t)(c * 2048) + (((uint32_t)(k * 2)) ^ swz);
            *(__half2*)(smem + SM_WH_HI + off) = __half2(h0, h1);
            *(__half2*)(smem + SM_WH_HI + off + 4) = __half2(h2, h3);
            *(__half2*)(smem + SM_WH_LO + off) = __half2(l0, l1);
            *(__half2*)(smem + SM_WH_LO + off + 4) = __half2(l2, l3);
        }
    }
    __syncthreads();

    // warp tile: rows [wm, wm+16), cols [wn, wn+16)
    const int wm = (wid >> 1) << 4;
    const int wn = (wid & 1) << 4;

    // A ldmatrix (16x16 tile, 256B rows, swizzled)
    const int ar = wm + (lane & 15);
    const uint32_t a_row = (uint32_t)ar * 256;
    const uint32_t a_k2 = (uint32_t)((lane >> 4) << 4);
    const uint32_t a_swz = (uint32_t)((ar & 7) << 4);

    // B ldmatrix (cols as rows, 2048B col stride, swizzled)
    const int bc = wn + (lane & 7) + ((lane >> 4) << 3);
    const uint32_t b_row = (uint32_t)bc * 2048;
    const uint32_t b_k2 = (uint32_t)(((lane >> 3) & 1) << 4);
    const uint32_t b_swz = (uint32_t)((bc & 7) << 4);

    // cp.async staging: row = tid>>2, 32 k elems (64B)
    const int srow = tid >> 2;
    const int skq = (tid & 3) * 32;
    const uint32_t s_swz = (uint32_t)((srow & 7) << 4);

    float creg[8];
#pragma unroll
    for (int q = 0; q < 8; q++) creg[q] = 0.0f;

    for (int s = 0; s < S_; s++) {
        const int p = s & 1;
        const __half* hsrc = g_hh[p];

        // xg prefetch for this step
        float4 xgr[8];
        if (wid < 2) {
            int b = wid * 32 + lane;
            const float* xp = g_xg + ((size_t)s * B_ + b) * HID + j0;
#pragma unroll
            for (int g = 0; g < 4; g++) {
                xgr[g * 2 + 0] = *(const float4*)(xp + g * HS);
                xgr[g * 2 + 1] = *(const float4*)(xp + g * HS + 4);
            }
        }

        float cA[4] = {0.f, 0.f, 0.f, 0.f};
        float cB[4] = {0.f, 0.f, 0.f, 0.f};

        // prologue: stage chunks 0,1,2 (three groups)
#pragma unroll
        for (int c0 = 0; c0 < 3; c0++) {
            const __half* src = hsrc + srow * HS + c0 * 128 + skq;
            uint32_t dbase = sb + SM_HST + (uint32_t)c0 * 16384u +
                             (uint32_t)srow * 256;
#pragma unroll
            for (int j = 0; j < 4; j++) {
                uint32_t sw = ((uint32_t)((skq + j * 8) * 2)) ^ s_swz;
                CP16(dbase + sw, src + j * 8);
            }
            CPCOMMIT();
        }

#pragma unroll 1
        for (int ch = 0; ch < 8; ch++) {
            CPWAIT(2);
            __syncthreads();
            // issue chunk ch+3 into ring buf (consumed in ch-1, safe after sync)
            if (ch < 5) {
                const int nc = ch + 3;
                const __half* src = hsrc + srow * HS + nc * 128 + skq;
                uint32_t dbase = sb + SM_HST + (uint32_t)(nc & 3) * 16384u +
                                 (uint32_t)srow * 256;
#pragma unroll
                for (int j = 0; j < 4; j++) {
                    uint32_t sw = ((uint32_t)((skq + j * 8) * 2)) ^ s_swz;
                    CP16(dbase + sw, src + j * 8);
                }
            }
            CPCOMMIT();

            const uint32_t abase = sb + SM_HST + (uint32_t)(ch & 3) * 16384u;
            const uint32_t kch2 = (uint32_t)(ch * 256);
#pragma unroll
            for (int k16 = 0; k16 < 8; k16++) {
                const uint32_t ka = (uint32_t)(k16 * 32);
                uint32_t ah0, ah1, ah2, ah3;
                LDSM4(ah0, ah1, ah2, ah3, abase + a_row + ((ka + a_k2) ^ a_swz));
                uint32_t bo = b_row + ((kch2 + ka + b_k2) ^ b_swz);
                uint32_t bh0, bh1, bh2, bh3, bl0, bl1, bl2, bl3;
                LDSM4(bh0, bh1, bh2, bh3, sb + SM_WH_HI + bo);
                LDSM4(bl0, bl1, bl2, bl3, sb + SM_WH_LO + bo);

                MMA16816(cA, ah0, ah1, ah2, ah3, bh0, bh1);
                MMA16816(cB, ah0, ah1, ah2, ah3, bh2, bh3);
                MMA16816(cA, ah0, ah1, ah2, ah3, bl0, bl1);
                MMA16816(cB, ah0, ah1, ah2, ah3, bl2, bl3);
            }
        }

        // scatter C frags to gates smem
        {
            const int tr = lane >> 2;
            const int tc = (lane & 3) * 2;
            const int br = wm + tr;
            gates[(br + 0) * 33 + wn + tc + 0] = cA[0];
            gates[(br + 0) * 33 + wn + tc + 1] = cA[1];
            gates[(br + 8) * 33 + wn + tc + 0] = cA[2];
            gates[(br + 8) * 33 + wn + tc + 1] = cA[3];
            gates[(br + 0) * 33 + wn + 8 + tc + 0] = cB[0];
            gates[(br + 0) * 33 + wn + 8 + tc + 1] = cB[1];
            gates[(br + 8) * 33 + wn + 8 + tc + 0] = cB[2];
            gates[(br + 8) * 33 + wn + 8 + tc + 1] = cB[3];
        }
        __syncthreads();

        // activations + state update (warps 0-1: one thread per batch)
        if (wid < 2) {
            const int b = wid * 32 + lane;
            const float* grow = gates + b * 33;
            float xi[8] = {xgr[0].x, xgr[0].y, xgr[0].z, xgr[0].w,
                           xgr[1].x, xgr[1].y, xgr[1].z, xgr[1].w};
            float xf[8] = {xgr[2].x, xgr[2].y, xgr[2].z, xgr[2].w,
                           xgr[3].x, xgr[3].y, xgr[3].z, xgr[3].w};
            float xg4[8] = {xgr[4].x, xgr[4].y, xgr[4].z, xgr[4].w,
                            xgr[5].x, xgr[5].y, xgr[5].z, xgr[5].w};
            float xo[8] = {xgr[6].x, xgr[6].y, xgr[6].z, xgr[6].w,
                           xgr[7].x, xgr[7].y, xgr[7].z, xgr[7].w};
            float hnew[8];
#pragma unroll
            for (int jl = 0; jl < 8; jl++) {
                float gi = grow[0 + jl] + xi[jl];
                float gf = grow[8 + jl] + xf[jl];
                float gg = grow[16 + jl] + xg4[jl];
                float go = grow[24 + jl] + xo[jl];
                float iv = sigf(gi);
                float fv = sigf(gf);
                float gv = tanhfast(gg);
                float ov = sigf(go);
                float c = fv * creg[jl] + iv * gv;
                creg[jl] = c;
                hnew[jl] = ov * tanhfast(c);
            }
            float* op = out + ((size_t)b * S_ + s) * HS + j0;
            *(float4*)(op + 0) = make_float4(hnew[0], hnew[1], hnew[2], hnew[3]);
            *(float4*)(op + 4) = make_float4(hnew[4], hnew[5], hnew[6], hnew[7]);

            union { __half2 v2[4]; uint4 u; } uh;
#pragma unroll
            for (int q = 0; q < 4; q++)
                uh.v2[q] = __half2(__float2half_rn(hnew[2 * q]),
                                   __float2half_rn(hnew[2 * q + 1]));
            *(uint4*)(&g_hh[p ^ 1][b * HS + j0]) = uh.u;

            if (do_tail && s == S_ - 1) {
                const size_t base = (size_t)B_ * S_ * HS;
                float* hp = out + base + (size_t)b * HS + j0;
                float* cp = out + base + (size_t)B_ * HS + (size_t)b * HS + j0;
                *(float4*)(hp + 0) = make_float4(hnew[0], hnew[1], hnew[2], hnew[3]);
                *(float4*)(hp + 4) = make_float4(hnew[4], hnew[5], hnew[6], hnew[7]);
                *(float4*)(cp + 0) = make_float4(creg[0], creg[1], creg[2], creg[3]);
                *(float4*)(cp + 4) = make_float4(creg[4], creg[5], creg[6], creg[7]);
            }
            __threadfence();
        }

        grid_barrier((unsigned)(s + 1) * (unsigned)gridDim.x);
    }
}

extern "C" void kernel_launch(void* const* d_in, const int* in_sizes, int n_in,
                              void* d_out, int out_size) {
    const float* x = (const float*)d_in[0];
    const float* wx = (const float*)d_in[1];
    const float* wh = (const float*)d_in[2];
    const float* bx = (const float*)d_in[3];
    const float* bh = (const float*)d_in[4];
    float* out = (float*)d_out;

    init_state<<<(B_ * HS / 2 + 255) / 256, 256>>>();
    convert_inputs<<<2048, 256>>>(x, wx);

    cudaFuncSetAttribute(xg_gemm_mma, cudaFuncAttributeMaxDynamicSharedMemorySize,
                         XG_SMEM);
    dim3 ga(S_ * B_ / 128, HID / 128);   // (256, 32)
    xg_gemm_mma<<<ga, 256, XG_SMEM>>>(bx, bh);

    cudaFuncSetAttribute(lstm_persist, cudaFuncAttributeMaxDynamicSharedMemorySize,
                         SMEM_TOTAL);
    int do_tail =
        ((long long)out_size >= (long long)B_ * S_ * HS + 2LL * B_ * HS) ? 1 : 0;
    lstm_persist<<<NCTA, THREADS, SMEM_TOTAL>>>(wh, out, do_tail);
}